// round 6
// baseline (speedup 1.0000x reference)
#include <cuda_runtime.h>
#include <stdint.h>

#define N_MAX   100000
#define E_MAX   1600000
#define D       64
#define DP      68                       // padded row stride (floats) to kill bank conflicts
#define NB_SCAN ((N_MAX + 255) / 256)

// ---------------- scratch (static device globals; no allocations) -------------
__device__ int    g_is64;
__device__ int    g_deg[N_MAX];
__device__ float  g_dinv[N_MAX];
__device__ int    g_rowptr[N_MAX + 1];
__device__ int    g_cursor[N_MAX];
__device__ int    g_bsum[NB_SCAN + 1];
__device__ int    g_bofs[NB_SCAN + 1];
__device__ int    g_row[E_MAX];
__device__ int    g_col[E_MAX];
__device__ float2 g_edge[E_MAX];         // packed {col(as float bits), lap}
__device__ float  g_tx1[(size_t)N_MAX * D];
__device__ float  g_tx2[(size_t)N_MAX * D];

// ---------------- dtype detection (int32 vs int64 edge_index) ------------------
__global__ void k_detect(const void* __restrict__ ei_raw, int n) {
    __shared__ int ok;
    int tid = threadIdx.x;
    if (tid == 0) ok = 1;
    __syncthreads();
    const long long* ei64 = (const long long*)ei_raw;
    long long v = ei64[tid];
    if (v < 0 || v >= (long long)n) ok = 0;
    __syncthreads();
    if (tid == 0) g_is64 = ok;
}

// ---------------- prep kernels -------------------------------------------------
__global__ void k_zero_deg(int n) {
    int i = blockIdx.x * blockDim.x + threadIdx.x;
    if (i < n) g_deg[i] = 0;
}

__global__ void k_prep(const void* __restrict__ ei_raw, int E) {
    int e = blockIdx.x * blockDim.x + threadIdx.x;
    if (e >= E) return;
    int r, c;
    if (g_is64) {
        const long long* ei = (const long long*)ei_raw;
        r = (int)ei[e];
        c = (int)ei[(size_t)E + e];
    } else {
        const int* ei = (const int*)ei_raw;
        r = ei[e];
        c = ei[(size_t)E + e];
    }
    g_row[e] = r;
    g_col[e] = c;
    atomicAdd(&g_deg[r], 1);
}

__global__ void k_scan1(int n) {
    __shared__ int s[256];
    int tid = threadIdx.x;
    int i = blockIdx.x * 256 + tid;
    int v = (i < n) ? g_deg[i] : 0;
    s[tid] = v;
    __syncthreads();
#pragma unroll
    for (int ofs = 1; ofs < 256; ofs <<= 1) {
        int t = (tid >= ofs) ? s[tid - ofs] : 0;
        __syncthreads();
        s[tid] += t;
        __syncthreads();
    }
    if (i < n) g_rowptr[i + 1] = s[tid];
    if (tid == 255) g_bsum[blockIdx.x] = s[255];
}

__global__ void k_scan2(int B) {
    __shared__ int s[512];
    int tid = threadIdx.x;
    int v = (tid < B) ? g_bsum[tid] : 0;
    s[tid] = v;
    __syncthreads();
#pragma unroll
    for (int ofs = 1; ofs < 512; ofs <<= 1) {
        int t = (tid >= ofs) ? s[tid - ofs] : 0;
        __syncthreads();
        s[tid] += t;
        __syncthreads();
    }
    if (tid < B) g_bofs[tid] = s[tid] - v;
}

__global__ void k_scan3(int n) {
    int i = blockIdx.x * blockDim.x + threadIdx.x;
    if (i >= n) return;
    int rp = g_rowptr[i + 1] + g_bofs[i >> 8];
    g_rowptr[i + 1] = rp;
    int dg = g_deg[i];
    g_cursor[i] = rp - dg;
    g_dinv[i] = (dg > 0) ? rsqrtf((float)dg) : 0.0f;
    if (i == 0) g_rowptr[0] = 0;
}

__global__ void k_scatter(const float* __restrict__ ea, int E) {
    int e = blockIdx.x * blockDim.x + threadIdx.x;
    if (e >= E) return;
    int r = g_row[e];
    int c = g_col[e];
    int p = atomicAdd(&g_cursor[r], 1);
    float lap = -g_dinv[r] * ea[e] * g_dinv[c];
    g_edge[p] = make_float2(__int_as_float(c), lap);   // single 8B store
}

// ---------------- fused SpMM + recurrence + block-cooperative GEMM -------------
//   K==1: t = spmm(x);           tx1=t; out = bias + x@W0 + t@W1
//   K==2: t = 2*spmm(tx1) - x;   tx2=t; out += t@W2
//   K==3: t = 2*spmm(tx2) - tx1;        out += t@W3
// Gather: one warp per node (lane covers 2 cols, coalesced 256B, L2-hit).
// Epilogue: block GEMM — warp w computes float2-cols [4w,4w+4) for ALL 8 rows,
// so W smem reads are shared 8-ways (broadcast) instead of duplicated per warp.
template <int K>
__global__ void __launch_bounds__(256) cheb_kernel(
    const float* __restrict__ h,        // T_{k-1}
    const float* __restrict__ prev,     // T_{k-2} (K>=2)
    const float* __restrict__ x,        // original x (K==1)
    const float* __restrict__ Wk,       // weight[k], 64x64 row-major
    const float* __restrict__ W0g,      // weight[0] (K==1)
    const float* __restrict__ bias,     // (K==1)
    float* __restrict__ out,
    int n)
{
    __shared__ float sW[D * D];
    __shared__ float sW0[(K == 1) ? (D * D) : 4];
    __shared__ float sT[8 * DP];
    __shared__ float sX[(K == 1) ? (8 * DP) : 4];

    int tid  = threadIdx.x;
    int warp = tid >> 5;
    int lane = tid & 31;

    for (int i = tid; i < D * D; i += 256) {
        sW[i] = Wk[i];
        if constexpr (K == 1) sW0[i] = W0g[i];
    }

    int r = blockIdx.x * 8 + warp;
    const unsigned FULL = 0xffffffffu;

    float2 t = make_float2(0.0f, 0.0f);
    if (r < n) {
        int s  = g_rowptr[r];
        int e2 = g_rowptr[r + 1];
        float2 acc = make_float2(0.0f, 0.0f);

        for (int base = s; base < e2; base += 32) {
            int m = e2 - base;
            if (m > 32) m = 32;
            float2 ev = make_float2(0.0f, 0.0f);
            if (lane < m) ev = g_edge[base + lane];
            int   cl = __float_as_int(ev.x);
            float ll = ev.y;
            int j = 0;
            for (; j + 4 <= m; j += 4) {
                int c0 = __shfl_sync(FULL, cl, j + 0);
                int c1 = __shfl_sync(FULL, cl, j + 1);
                int c2 = __shfl_sync(FULL, cl, j + 2);
                int c3 = __shfl_sync(FULL, cl, j + 3);
                float l0 = __shfl_sync(FULL, ll, j + 0);
                float l1 = __shfl_sync(FULL, ll, j + 1);
                float l2 = __shfl_sync(FULL, ll, j + 2);
                float l3 = __shfl_sync(FULL, ll, j + 3);
                float2 h0 = *reinterpret_cast<const float2*>(h + (size_t)c0 * D + lane * 2);
                float2 h1 = *reinterpret_cast<const float2*>(h + (size_t)c1 * D + lane * 2);
                float2 h2 = *reinterpret_cast<const float2*>(h + (size_t)c2 * D + lane * 2);
                float2 h3 = *reinterpret_cast<const float2*>(h + (size_t)c3 * D + lane * 2);
                acc.x = fmaf(l0, h0.x, acc.x); acc.y = fmaf(l0, h0.y, acc.y);
                acc.x = fmaf(l1, h1.x, acc.x); acc.y = fmaf(l1, h1.y, acc.y);
                acc.x = fmaf(l2, h2.x, acc.x); acc.y = fmaf(l2, h2.y, acc.y);
                acc.x = fmaf(l3, h3.x, acc.x); acc.y = fmaf(l3, h3.y, acc.y);
            }
            for (; j < m; ++j) {
                int   cj = __shfl_sync(FULL, cl, j);
                float lj = __shfl_sync(FULL, ll, j);
                float2 hv = *reinterpret_cast<const float2*>(h + (size_t)cj * D + lane * 2);
                acc.x = fmaf(lj, hv.x, acc.x);
                acc.y = fmaf(lj, hv.y, acc.y);
            }
        }

        // Chebyshev recurrence
        if constexpr (K == 1) {
            t = acc;
        } else {
            float2 pv = *reinterpret_cast<const float2*>(prev + (size_t)r * D + lane * 2);
            t.x = 2.0f * acc.x - pv.x;
            t.y = 2.0f * acc.y - pv.y;
        }
        if constexpr (K == 1)
            *reinterpret_cast<float2*>(g_tx1 + (size_t)r * D + lane * 2) = t;
        if constexpr (K == 2)
            *reinterpret_cast<float2*>(g_tx2 + (size_t)r * D + lane * 2) = t;

        sT[warp * DP + lane * 2 + 0] = t.x;
        sT[warp * DP + lane * 2 + 1] = t.y;
        if constexpr (K == 1) {
            float2 xv = *reinterpret_cast<const float2*>(x + (size_t)r * D + lane * 2);
            sX[warp * DP + lane * 2 + 0] = xv.x;
            sX[warp * DP + lane * 2 + 1] = xv.y;
        }
    }
    __syncthreads();

    // ---- block GEMM: O[8][64] (+)= T[8][64] @ Wk (+ X @ W0 + bias for K==1) ----
    int r8   = lane >> 2;                  // row within block 0..7
    int cp   = (warp << 2) + (lane & 3);   // float2 column 0..31
    int node = blockIdx.x * 8 + r8;

    float2 o;
    if constexpr (K == 1) {
        o = reinterpret_cast<const float2*>(bias)[cp];
    } else {
        o = (node < n) ? reinterpret_cast<const float2*>(out)[(size_t)node * 32 + cp]
                       : make_float2(0.0f, 0.0f);
    }

    const float2* Wp  = reinterpret_cast<const float2*>(sW);
    const float*  Trow = sT + r8 * DP;
#pragma unroll 16
    for (int i = 0; i < D; ++i) {
        float  tv = Trow[i];
        float2 w  = Wp[i * 32 + cp];
        o.x = fmaf(tv, w.x, o.x);
        o.y = fmaf(tv, w.y, o.y);
    }
    if constexpr (K == 1) {
        const float2* W0p  = reinterpret_cast<const float2*>(sW0);
        const float*  Xrow = sX + r8 * DP;
#pragma unroll 16
        for (int i = 0; i < D; ++i) {
            float  xv = Xrow[i];
            float2 w  = W0p[i * 32 + cp];
            o.x = fmaf(xv, w.x, o.x);
            o.y = fmaf(xv, w.y, o.y);
        }
    }

    if (node < n)
        reinterpret_cast<float2*>(out)[(size_t)node * 32 + cp] = o;
}

// ---------------- launch -------------------------------------------------------
extern "C" void kernel_launch(void* const* d_in, const int* in_sizes, int n_in,
                              void* d_out, int out_size)
{
    const float* x   = (const float*)d_in[0];
    const void*  ei  = d_in[1];
    const float* ea  = (const float*)d_in[2];
    const float* w   = (const float*)d_in[3];
    const float* b   = (const float*)d_in[4];
    float*       out = (float*)d_out;

    int n = in_sizes[0] / D;
    int E = in_sizes[2];

    int nbN = (n + 255) / 256;
    int nbE = (E + 255) / 256;

    k_detect<<<1, 256>>>(ei, n);
    k_zero_deg<<<nbN, 256>>>(n);
    k_prep<<<nbE, 256>>>(ei, E);
    k_scan1<<<nbN, 256>>>(n);
    k_scan2<<<1, 512>>>(nbN);
    k_scan3<<<nbN, 256>>>(n);
    k_scatter<<<nbE, 256>>>(ea, E);

    float* tx1;  cudaGetSymbolAddress((void**)&tx1, g_tx1);
    float* tx2;  cudaGetSymbolAddress((void**)&tx2, g_tx2);

    int gb = (n + 7) / 8;
    cheb_kernel<1><<<gb, 256>>>(x,   nullptr, x, w + 1 * D * D, w, b, out, n);
    cheb_kernel<2><<<gb, 256>>>(tx1, x,   nullptr, w + 2 * D * D, nullptr, nullptr, out, n);
    cheb_kernel<3><<<gb, 256>>>(tx2, tx1, nullptr, w + 3 * D * D, nullptr, nullptr, out, n);
}

// round 9
// speedup vs baseline: 1.7205x; 1.7205x over previous
#include <cuda_runtime.h>
#include <stdint.h>

#define N_MAX   100000
#define E_MAX   1600000
#define D       64

// ---------------- scratch (static device globals; no allocations) -------------
__device__ int    g_is64;
__device__ int    g_total;
__device__ int    g_deg[N_MAX];
__device__ float  g_dinv[N_MAX];
__device__ int    g_rowstart[N_MAX];
__device__ int    g_cursor[N_MAX];
__device__ int    g_row[E_MAX];
__device__ int    g_col[E_MAX];
__device__ float2 g_edge[E_MAX];          // packed {col(bits), lap}
__device__ float  g_tx1[(size_t)N_MAX * D];
__device__ float  g_tx2[(size_t)N_MAX * D];
__device__ float  g_tx3[(size_t)N_MAX * D];

// ---------------- f32x2 helpers -------------------------------------------------
__device__ __forceinline__ unsigned long long pk2(float a, float b) {
    unsigned long long r;
    asm("mov.b64 %0, {%1, %2};" : "=l"(r) : "f"(a), "f"(b));
    return r;
}
__device__ __forceinline__ void upk2(unsigned long long v, float& a, float& b) {
    asm("mov.b64 {%0, %1}, %2;" : "=f"(a), "=f"(b) : "l"(v));
}
__device__ __forceinline__ void fma2(unsigned long long& d,
                                     unsigned long long a, unsigned long long b) {
    asm("fma.rn.f32x2 %0, %1, %2, %0;" : "+l"(d) : "l"(a), "l"(b));
}

// ---------------- prep -----------------------------------------------------------
// init: zero degrees + zero total + dtype-detect (int32 vs int64 edge_index)
__global__ void k_init(const void* __restrict__ ei_raw, int n) {
    int i = blockIdx.x * 256 + threadIdx.x;
    if (i < n) g_deg[i] = 0;
    if (blockIdx.x == 0) {
        if (threadIdx.x == 0) { g_total = 0; g_is64 = 1; }
        __syncthreads();
        const long long* e64 = (const long long*)ei_raw;
        long long v = e64[threadIdx.x];
        if (v < 0 || v >= (long long)n) g_is64 = 0;   // any OOB => int32 data
    }
}

__global__ void k_prep(const void* __restrict__ ei_raw, int E) {
    int e = blockIdx.x * blockDim.x + threadIdx.x;
    if (e >= E) return;
    int r, c;
    if (g_is64) {
        const long long* ei = (const long long*)ei_raw;
        r = (int)ei[e];
        c = (int)ei[(size_t)E + e];
    } else {
        const int* ei = (const int*)ei_raw;
        r = ei[e];
        c = ei[(size_t)E + e];
    }
    g_row[e] = r;
    g_col[e] = c;
    atomicAdd(&g_deg[r], 1);
}

// atomic segment allocation (order of segments is irrelevant for a gather)
__global__ void k_offsets(int n) {
    int i = blockIdx.x * blockDim.x + threadIdx.x;
    if (i >= n) return;
    int dg = g_deg[i];
    int st = atomicAdd(&g_total, dg);
    g_rowstart[i] = st;
    g_cursor[i]   = st;
    g_dinv[i]     = (dg > 0) ? rsqrtf((float)dg) : 0.0f;
}

__global__ void k_scatter(const float* __restrict__ ea, int E) {
    int e = blockIdx.x * blockDim.x + threadIdx.x;
    if (e >= E) return;
    int r = g_row[e];
    int c = g_col[e];
    int p = atomicAdd(&g_cursor[r], 1);
    float lap = -g_dinv[r] * ea[e] * g_dinv[c];
    g_edge[p] = make_float2(__int_as_float(c), lap);
}

// ---------------- lean SpMM (one warp per node, no smem, no block sync) ----------
//   K==1: dst = A_hat @ x
//   K>=2: dst = 2 * A_hat @ h - prev
template <int K>
__global__ void __launch_bounds__(256) spmm_kernel(
    const float* __restrict__ h,
    const float* __restrict__ prev,
    float* __restrict__ dst,
    int n)
{
    int warp = threadIdx.x >> 5;
    int lane = threadIdx.x & 31;
    int r = blockIdx.x * 8 + warp;
    if (r >= n) return;

    int s  = g_rowstart[r];
    int mN = g_deg[r];
    const unsigned FULL = 0xffffffffu;

    float2 acc = make_float2(0.0f, 0.0f);
    for (int base = 0; base < mN; base += 32) {
        int m = mN - base;
        if (m > 32) m = 32;
        float2 ev = make_float2(0.0f, 0.0f);
        if (lane < m) ev = g_edge[s + base + lane];
        int   cl = __float_as_int(ev.x);
        float ll = ev.y;
        int j = 0;
        for (; j + 4 <= m; j += 4) {
            int c0 = __shfl_sync(FULL, cl, j + 0);
            int c1 = __shfl_sync(FULL, cl, j + 1);
            int c2 = __shfl_sync(FULL, cl, j + 2);
            int c3 = __shfl_sync(FULL, cl, j + 3);
            float l0 = __shfl_sync(FULL, ll, j + 0);
            float l1 = __shfl_sync(FULL, ll, j + 1);
            float l2 = __shfl_sync(FULL, ll, j + 2);
            float l3 = __shfl_sync(FULL, ll, j + 3);
            float2 h0 = *reinterpret_cast<const float2*>(h + (size_t)c0 * D + lane * 2);
            float2 h1 = *reinterpret_cast<const float2*>(h + (size_t)c1 * D + lane * 2);
            float2 h2 = *reinterpret_cast<const float2*>(h + (size_t)c2 * D + lane * 2);
            float2 h3 = *reinterpret_cast<const float2*>(h + (size_t)c3 * D + lane * 2);
            acc.x = fmaf(l0, h0.x, acc.x); acc.y = fmaf(l0, h0.y, acc.y);
            acc.x = fmaf(l1, h1.x, acc.x); acc.y = fmaf(l1, h1.y, acc.y);
            acc.x = fmaf(l2, h2.x, acc.x); acc.y = fmaf(l2, h2.y, acc.y);
            acc.x = fmaf(l3, h3.x, acc.x); acc.y = fmaf(l3, h3.y, acc.y);
        }
        for (; j < m; ++j) {
            int   cj = __shfl_sync(FULL, cl, j);
            float lj = __shfl_sync(FULL, ll, j);
            float2 hv = *reinterpret_cast<const float2*>(h + (size_t)cj * D + lane * 2);
            acc.x = fmaf(lj, hv.x, acc.x);
            acc.y = fmaf(lj, hv.y, acc.y);
        }
    }

    float2 t;
    if constexpr (K == 1) {
        t = acc;
    } else {
        float2 pv = *reinterpret_cast<const float2*>(prev + (size_t)r * D + lane * 2);
        t.x = 2.0f * acc.x - pv.x;
        t.y = 2.0f * acc.y - pv.y;
    }
    *reinterpret_cast<float2*>(dst + (size_t)r * D + lane * 2) = t;
}

// ---------------- dense GEMM: out = [x|T1|T2|T3] @ W(256x64) + bias --------------
// Block: 128 rows x 64 cols, 256 threads; thread tile 8 rows x 4 cols.
// Rows packed in f32x2 pairs (natural from transposed smem A-tile);
// W duplicated per col via mov.b64 (alu pipe) -> fma-pipe work halved.
#define GBM 128
#define ATS 132   // padded smem stride (floats), 16B-aligned

__global__ void __launch_bounds__(256) gemm_kernel(
    const float* __restrict__ x,
    const float* __restrict__ w,      // [4][64][64] = 256x64 row-major stacked
    const float* __restrict__ bias,
    float* __restrict__ out,
    int n)
{
    __shared__ float sW[D * D];        // current 64x64 W chunk
    __shared__ float sAT[D][ATS];      // transposed A chunk: sAT[k][m]

    int tid  = threadIdx.x;
    int c4   = (tid & 15) << 2;        // col base 0..60
    int r8   = (tid >> 4) << 3;        // row base 0..120
    int base = blockIdx.x * GBM;

    unsigned long long acc[4][4];      // [col j][row-pair p]
#pragma unroll
    for (int j = 0; j < 4; ++j)
#pragma unroll
        for (int p = 0; p < 4; ++p) acc[j][p] = 0ull;

    const float* srcs[4] = { x, g_tx1, g_tx2, g_tx3 };

#pragma unroll
    for (int sIdx = 0; sIdx < 4; ++sIdx) {
        const float* src = srcs[sIdx];
        __syncthreads();               // protect smem from previous chunk readers
        // stage W chunk (coalesced float4)
        {
            const float4* wsrc = (const float4*)(w + sIdx * (D * D));
            for (int i = tid; i < (D * D) / 4; i += 256)
                ((float4*)sW)[i] = wsrc[i];
        }
        // stage A chunk transposed: thread covers row m=tid/2, half = 32 cols
        {
            int m    = tid >> 1;
            int half = (tid & 1) << 5;
            int row  = base + m;
#pragma unroll
            for (int i = 0; i < 8; ++i) {
                float4 f = make_float4(0.f, 0.f, 0.f, 0.f);
                if (row < n)
                    f = *(const float4*)(src + (size_t)row * D + half + i * 4);
                int k = half + i * 4;
                sAT[k + 0][m] = f.x;
                sAT[k + 1][m] = f.y;
                sAT[k + 2][m] = f.z;
                sAT[k + 3][m] = f.w;
            }
        }
        __syncthreads();

#pragma unroll 4
        for (int k = 0; k < D; ++k) {
            // 8 row values as 4 natural f32x2 pairs (16-lane broadcast loads)
            ulonglong2 aA = *(const ulonglong2*)&sAT[k][r8];
            ulonglong2 aB = *(const ulonglong2*)&sAT[k][r8 + 4];
            float4 w4 = *(const float4*)&sW[k * D + c4];
            unsigned long long w0 = pk2(w4.x, w4.x);
            unsigned long long w1 = pk2(w4.y, w4.y);
            unsigned long long w2 = pk2(w4.z, w4.z);
            unsigned long long w3 = pk2(w4.w, w4.w);
            fma2(acc[0][0], aA.x, w0); fma2(acc[0][1], aA.y, w0);
            fma2(acc[0][2], aB.x, w0); fma2(acc[0][3], aB.y, w0);
            fma2(acc[1][0], aA.x, w1); fma2(acc[1][1], aA.y, w1);
            fma2(acc[1][2], aB.x, w1); fma2(acc[1][3], aB.y, w1);
            fma2(acc[2][0], aA.x, w2); fma2(acc[2][1], aA.y, w2);
            fma2(acc[2][2], aB.x, w2); fma2(acc[2][3], aB.y, w2);
            fma2(acc[3][0], aA.x, w3); fma2(acc[3][1], aA.y, w3);
            fma2(acc[3][2], aB.x, w3); fma2(acc[3][3], aB.y, w3);
        }
    }

    // epilogue: unpack, add bias, store 8 rows x float4
    float4 b4 = *(const float4*)(bias + c4);
#pragma unroll
    for (int p = 0; p < 4; ++p) {
        float o0[4], o1[4];            // row 2p (lo) and row 2p+1 (hi), 4 cols
#pragma unroll
        for (int j = 0; j < 4; ++j) upk2(acc[j][p], o0[j], o1[j]);
        int row0 = base + r8 + 2 * p;
        if (row0 < n) {
            float4 o = make_float4(o0[0] + b4.x, o0[1] + b4.y,
                                   o0[2] + b4.z, o0[3] + b4.w);
            *(float4*)(out + (size_t)row0 * D + c4) = o;
        }
        if (row0 + 1 < n) {
            float4 o = make_float4(o1[0] + b4.x, o1[1] + b4.y,
                                   o1[2] + b4.z, o1[3] + b4.w);
            *(float4*)(out + (size_t)(row0 + 1) * D + c4) = o;
        }
    }
}

// ---------------- launch -----------------------------------------------------------
extern "C" void kernel_launch(void* const* d_in, const int* in_sizes, int n_in,
                              void* d_out, int out_size)
{
    const float* x   = (const float*)d_in[0];
    const void*  ei  = d_in[1];
    const float* ea  = (const float*)d_in[2];
    const float* w   = (const float*)d_in[3];
    const float* b   = (const float*)d_in[4];
    float*       out = (float*)d_out;

    int n = in_sizes[0] / D;
    int E = in_sizes[2];

    int nbN = (n + 255) / 256;
    int nbE = (E + 255) / 256;

    float *tx1, *tx2, *tx3;
    cudaGetSymbolAddress((void**)&tx1, g_tx1);
    cudaGetSymbolAddress((void**)&tx2, g_tx2);
    cudaGetSymbolAddress((void**)&tx3, g_tx3);

    k_init<<<nbN, 256>>>(ei, n);
    k_prep<<<nbE, 256>>>(ei, E);
    k_offsets<<<nbN, 256>>>(n);
    k_scatter<<<nbE, 256>>>(ea, E);

    int gs = (n + 7) / 8;
    spmm_kernel<1><<<gs, 256>>>(x,   nullptr, tx1, n);
    spmm_kernel<2><<<gs, 256>>>(tx1, x,       tx2, n);
    spmm_kernel<3><<<gs, 256>>>(tx2, tx1,     tx3, n);

    gemm_kernel<<<(n + GBM - 1) / GBM, 256>>>(x, w, b, out, n);
}

// round 10
// speedup vs baseline: 1.7604x; 1.0232x over previous
#include <cuda_runtime.h>
#include <stdint.h>

#define N_MAX   100000
#define E_MAX   1600000
#define D       64

// ---------------- scratch (static device globals; no allocations) -------------
__device__ int    g_is64;
__device__ int    g_total;
__device__ int    g_deg[N_MAX];
__device__ float  g_dinv[N_MAX];
__device__ int    g_rowstart[N_MAX];
__device__ int    g_cursor[N_MAX];
__device__ float2 g_edge[E_MAX];          // packed {col(bits), ea*dinv[col]}
__device__ float  g_tx1[(size_t)N_MAX * D];
__device__ float  g_tx2[(size_t)N_MAX * D];
__device__ float  g_tx3[(size_t)N_MAX * D];

// ---------------- f32x2 helpers -------------------------------------------------
__device__ __forceinline__ unsigned long long pk2(float a, float b) {
    unsigned long long r;
    asm("mov.b64 %0, {%1, %2};" : "=l"(r) : "f"(a), "f"(b));
    return r;
}
__device__ __forceinline__ void upk2(unsigned long long v, float& a, float& b) {
    asm("mov.b64 {%0, %1}, %2;" : "=f"(a), "=f"(b) : "l"(v));
}
__device__ __forceinline__ void fma2(unsigned long long& d,
                                     unsigned long long a, unsigned long long b) {
    asm("fma.rn.f32x2 %0, %1, %2, %0;" : "+l"(d) : "l"(a), "l"(b));
}

// ---------------- prep -----------------------------------------------------------
// dtype-detect (int32 vs int64 edge_index) + zero total
__global__ void k_detect(const void* __restrict__ ei_raw, int n) {
    if (threadIdx.x == 0) { g_total = 0; g_is64 = 1; }
    __syncthreads();
    const long long* e64 = (const long long*)ei_raw;
    long long v = e64[threadIdx.x];
    if (v < 0 || v >= (long long)n) g_is64 = 0;   // any OOB => int32 data
}

__global__ void k_prep(const void* __restrict__ ei_raw, int E) {
    int e = blockIdx.x * blockDim.x + threadIdx.x;
    if (e >= E) return;
    int r;
    if (g_is64) r = (int)((const long long*)ei_raw)[e];
    else        r = ((const int*)ei_raw)[e];
    atomicAdd(&g_deg[r], 1);
}

// atomic segment allocation (order of segments is irrelevant for a gather)
__global__ void k_offsets(int n) {
    int i = blockIdx.x * blockDim.x + threadIdx.x;
    if (i >= n) return;
    int dg = g_deg[i];
    int st = atomicAdd(&g_total, dg);
    g_rowstart[i] = st;
    g_cursor[i]   = st;
    g_dinv[i]     = (dg > 0) ? rsqrtf((float)dg) : 0.0f;
}

__global__ void k_scatter(const void* __restrict__ ei_raw,
                          const float* __restrict__ ea, int E) {
    int e = blockIdx.x * blockDim.x + threadIdx.x;
    if (e >= E) return;
    int r, c;
    if (g_is64) {
        const long long* ei = (const long long*)ei_raw;
        r = (int)ei[e];
        c = (int)ei[(size_t)E + e];
    } else {
        const int* ei = (const int*)ei_raw;
        r = ei[e];
        c = ei[(size_t)E + e];
    }
    int p = atomicAdd(&g_cursor[r], 1);
    // dinv[r] factored out (applied per-node in spmm) -> one less random gather
    g_edge[p] = make_float2(__int_as_float(c), ea[e] * g_dinv[c]);
}

// ---------------- lean SpMM: 2 nodes per warp, float4 gathers --------------------
//   acc = sum_e (ea*dinv[c]) * h[c];  t = (-dinv[r]) * acc            (K==1)
//                                      t = 2*(-dinv[r])*acc - prev    (K>=2)
template <int K>
__global__ void __launch_bounds__(256) spmm_kernel(
    const float* __restrict__ h,
    const float* __restrict__ prev,
    float* __restrict__ dst,
    int n)
{
    int tid  = threadIdx.x;
    int warp = tid >> 5;
    int lane = tid & 31;
    int half = lane >> 4;                 // 0 or 1: which node this half-warp owns
    int hl   = lane & 15;                 // lane within half
    unsigned hmask = 0xFFFFu << (half << 4);

    int r = blockIdx.x * 16 + warp * 2 + half;
    bool valid = (r < n);

    int   s = 0, mN = 0;
    float scale = 0.0f;
    if (valid) {
        s     = g_rowstart[r];
        mN    = g_deg[r];
        scale = -g_dinv[r];
    }

    float4 acc = make_float4(0.0f, 0.0f, 0.0f, 0.0f);

    for (int base = 0; base < mN; base += 16) {
        int m = mN - base;
        if (m > 16) m = 16;
        float2 ev = make_float2(0.0f, 0.0f);
        if (hl < m) ev = g_edge[s + base + hl];
        int   cl = __float_as_int(ev.x);
        float ll = ev.y;

        int j = 0;
        for (; j + 4 <= m; j += 4) {
            int c0 = __shfl_sync(hmask, cl, j + 0, 16);
            int c1 = __shfl_sync(hmask, cl, j + 1, 16);
            int c2 = __shfl_sync(hmask, cl, j + 2, 16);
            int c3 = __shfl_sync(hmask, cl, j + 3, 16);
            float l0 = __shfl_sync(hmask, ll, j + 0, 16);
            float l1 = __shfl_sync(hmask, ll, j + 1, 16);
            float l2 = __shfl_sync(hmask, ll, j + 2, 16);
            float l3 = __shfl_sync(hmask, ll, j + 3, 16);
            float4 h0 = *(const float4*)(h + (size_t)c0 * D + hl * 4);
            float4 h1 = *(const float4*)(h + (size_t)c1 * D + hl * 4);
            float4 h2 = *(const float4*)(h + (size_t)c2 * D + hl * 4);
            float4 h3 = *(const float4*)(h + (size_t)c3 * D + hl * 4);
            acc.x = fmaf(l0, h0.x, acc.x); acc.y = fmaf(l0, h0.y, acc.y);
            acc.z = fmaf(l0, h0.z, acc.z); acc.w = fmaf(l0, h0.w, acc.w);
            acc.x = fmaf(l1, h1.x, acc.x); acc.y = fmaf(l1, h1.y, acc.y);
            acc.z = fmaf(l1, h1.z, acc.z); acc.w = fmaf(l1, h1.w, acc.w);
            acc.x = fmaf(l2, h2.x, acc.x); acc.y = fmaf(l2, h2.y, acc.y);
            acc.z = fmaf(l2, h2.z, acc.z); acc.w = fmaf(l2, h2.w, acc.w);
            acc.x = fmaf(l3, h3.x, acc.x); acc.y = fmaf(l3, h3.y, acc.y);
            acc.z = fmaf(l3, h3.z, acc.z); acc.w = fmaf(l3, h3.w, acc.w);
        }
        for (; j < m; ++j) {
            int   cj = __shfl_sync(hmask, cl, j, 16);
            float lj = __shfl_sync(hmask, ll, j, 16);
            float4 hv = *(const float4*)(h + (size_t)cj * D + hl * 4);
            acc.x = fmaf(lj, hv.x, acc.x); acc.y = fmaf(lj, hv.y, acc.y);
            acc.z = fmaf(lj, hv.z, acc.z); acc.w = fmaf(lj, hv.w, acc.w);
        }
    }

    if (!valid) return;

    float4 t;
    if constexpr (K == 1) {
        t = make_float4(scale * acc.x, scale * acc.y, scale * acc.z, scale * acc.w);
    } else {
        float4 pv = *(const float4*)(prev + (size_t)r * D + hl * 4);
        float s2 = 2.0f * scale;
        t = make_float4(fmaf(s2, acc.x, -pv.x), fmaf(s2, acc.y, -pv.y),
                        fmaf(s2, acc.z, -pv.z), fmaf(s2, acc.w, -pv.w));
    }
    *(float4*)(dst + (size_t)r * D + hl * 4) = t;
}

// ---------------- dense GEMM: out = [x|T1|T2|T3] @ W(256x64) + bias --------------
// Block: 128 rows x 64 cols, 256 threads; thread tile 8 rows x 4 cols, f32x2 FMAs.
#define GBM 128
#define ATS 132   // padded smem stride (floats), 16B-aligned

__global__ void __launch_bounds__(256) gemm_kernel(
    const float* __restrict__ x,
    const float* __restrict__ w,      // [4][64][64] stacked
    const float* __restrict__ bias,
    float* __restrict__ out,
    int n)
{
    __shared__ float sW[D * D];
    __shared__ float sAT[D][ATS];      // transposed A chunk: sAT[k][m]

    int tid  = threadIdx.x;
    int c4   = (tid & 15) << 2;        // col base 0..60
    int r8   = (tid >> 4) << 3;        // row base 0..120
    int base = blockIdx.x * GBM;

    unsigned long long acc[4][4];
#pragma unroll
    for (int j = 0; j < 4; ++j)
#pragma unroll
        for (int p = 0; p < 4; ++p) acc[j][p] = 0ull;

    const float* srcs[4] = { x, g_tx1, g_tx2, g_tx3 };

#pragma unroll
    for (int sIdx = 0; sIdx < 4; ++sIdx) {
        const float* src = srcs[sIdx];
        __syncthreads();
        {
            const float4* wsrc = (const float4*)(w + sIdx * (D * D));
            for (int i = tid; i < (D * D) / 4; i += 256)
                ((float4*)sW)[i] = wsrc[i];
        }
        {
            int m    = tid >> 1;
            int half = (tid & 1) << 5;
            int row  = base + m;
#pragma unroll
            for (int i = 0; i < 8; ++i) {
                float4 f = make_float4(0.f, 0.f, 0.f, 0.f);
                if (row < n)
                    f = *(const float4*)(src + (size_t)row * D + half + i * 4);
                int k = half + i * 4;
                sAT[k + 0][m] = f.x;
                sAT[k + 1][m] = f.y;
                sAT[k + 2][m] = f.z;
                sAT[k + 3][m] = f.w;
            }
        }
        __syncthreads();

#pragma unroll 4
        for (int k = 0; k < D; ++k) {
            ulonglong2 aA = *(const ulonglong2*)&sAT[k][r8];
            ulonglong2 aB = *(const ulonglong2*)&sAT[k][r8 + 4];
            float4 w4 = *(const float4*)&sW[k * D + c4];
            unsigned long long w0 = pk2(w4.x, w4.x);
            unsigned long long w1 = pk2(w4.y, w4.y);
            unsigned long long w2 = pk2(w4.z, w4.z);
            unsigned long long w3 = pk2(w4.w, w4.w);
            fma2(acc[0][0], aA.x, w0); fma2(acc[0][1], aA.y, w0);
            fma2(acc[0][2], aB.x, w0); fma2(acc[0][3], aB.y, w0);
            fma2(acc[1][0], aA.x, w1); fma2(acc[1][1], aA.y, w1);
            fma2(acc[1][2], aB.x, w1); fma2(acc[1][3], aB.y, w1);
            fma2(acc[2][0], aA.x, w2); fma2(acc[2][1], aA.y, w2);
            fma2(acc[2][2], aB.x, w2); fma2(acc[2][3], aB.y, w2);
            fma2(acc[3][0], aA.x, w3); fma2(acc[3][1], aA.y, w3);
            fma2(acc[3][2], aB.x, w3); fma2(acc[3][3], aB.y, w3);
        }
    }

    float4 b4 = *(const float4*)(bias + c4);
#pragma unroll
    for (int p = 0; p < 4; ++p) {
        float o0[4], o1[4];
#pragma unroll
        for (int j = 0; j < 4; ++j) upk2(acc[j][p], o0[j], o1[j]);
        int row0 = base + r8 + 2 * p;
        if (row0 < n) {
            float4 o = make_float4(o0[0] + b4.x, o0[1] + b4.y,
                                   o0[2] + b4.z, o0[3] + b4.w);
            *(float4*)(out + (size_t)row0 * D + c4) = o;
        }
        if (row0 + 1 < n) {
            float4 o = make_float4(o1[0] + b4.x, o1[1] + b4.y,
                                   o1[2] + b4.z, o1[3] + b4.w);
            *(float4*)(out + (size_t)(row0 + 1) * D + c4) = o;
        }
    }
}

// ---------------- launch -----------------------------------------------------------
extern "C" void kernel_launch(void* const* d_in, const int* in_sizes, int n_in,
                              void* d_out, int out_size)
{
    const float* x   = (const float*)d_in[0];
    const void*  ei  = d_in[1];
    const float* ea  = (const float*)d_in[2];
    const float* w   = (const float*)d_in[3];
    const float* b   = (const float*)d_in[4];
    float*       out = (float*)d_out;

    int n = in_sizes[0] / D;
    int E = in_sizes[2];

    int nbN = (n + 255) / 256;
    int nbE = (E + 255) / 256;

    float *tx1, *tx2, *tx3;
    cudaGetSymbolAddress((void**)&tx1, g_tx1);
    cudaGetSymbolAddress((void**)&tx2, g_tx2);
    cudaGetSymbolAddress((void**)&tx3, g_tx3);

    void* degp; cudaGetSymbolAddress(&degp, g_deg);
    cudaMemsetAsync(degp, 0, (size_t)n * sizeof(int));

    k_detect<<<1, 256>>>(ei, n);
    k_prep<<<nbE, 256>>>(ei, E);
    k_offsets<<<nbN, 256>>>(n);
    k_scatter<<<nbE, 256>>>(ei, ea, E);

    int gs = (n + 15) / 16;   // 16 nodes per block (2 per warp)
    spmm_kernel<1><<<gs, 256>>>(x,   nullptr, tx1, n);
    spmm_kernel<2><<<gs, 256>>>(tx1, x,       tx2, n);
    spmm_kernel<3><<<gs, 256>>>(tx2, tx1,     tx3, n);

    gemm_kernel<<<(n + GBM - 1) / GBM, 256>>>(x, w, b, out, n);
}

// round 11
// speedup vs baseline: 2.2381x; 1.2714x over previous
#include <cuda_runtime.h>
#include <stdint.h>

#define N_MAX   100000
#define E_MAX   1600000
#define D       64

// ---------------- scratch (static device globals; no allocations) -------------
__device__ int    g_is64;
__device__ int    g_total;
__device__ int    g_deg[N_MAX];
__device__ float  g_dinv[N_MAX];
__device__ int    g_rowstart[N_MAX];
__device__ int    g_cursor[N_MAX];
__device__ float2 g_edge[E_MAX];          // packed {col(bits), ea*dinv[col]}
__device__ float  g_tx1[(size_t)N_MAX * D];
__device__ float  g_tx2[(size_t)N_MAX * D];
__device__ float  g_tx3[(size_t)N_MAX * D];

// ---------------- prep -----------------------------------------------------------
__global__ void k_detect(const void* __restrict__ ei_raw, int n) {
    if (threadIdx.x == 0) { g_total = 0; g_is64 = 1; }
    __syncthreads();
    const long long* e64 = (const long long*)ei_raw;
    long long v = e64[threadIdx.x];
    if (v < 0 || v >= (long long)n) g_is64 = 0;   // any OOB => int32 data
}

__global__ void k_prep(const void* __restrict__ ei_raw, int E) {
    int e = blockIdx.x * blockDim.x + threadIdx.x;
    if (e >= E) return;
    int r;
    if (g_is64) r = (int)((const long long*)ei_raw)[e];
    else        r = ((const int*)ei_raw)[e];
    atomicAdd(&g_deg[r], 1);
}

__global__ void k_offsets(int n) {
    int i = blockIdx.x * blockDim.x + threadIdx.x;
    if (i >= n) return;
    int dg = g_deg[i];
    int st = atomicAdd(&g_total, dg);
    g_rowstart[i] = st;
    g_cursor[i]   = st;
    g_dinv[i]     = (dg > 0) ? rsqrtf((float)dg) : 0.0f;
}

__global__ void k_scatter(const void* __restrict__ ei_raw,
                          const float* __restrict__ ea, int E) {
    int e = blockIdx.x * blockDim.x + threadIdx.x;
    if (e >= E) return;
    int r, c;
    if (g_is64) {
        const long long* ei = (const long long*)ei_raw;
        r = (int)ei[e];
        c = (int)ei[(size_t)E + e];
    } else {
        const int* ei = (const int*)ei_raw;
        r = ei[e];
        c = ei[(size_t)E + e];
    }
    int p = atomicAdd(&g_cursor[r], 1);
    g_edge[p] = make_float2(__int_as_float(c), ea[e] * g_dinv[c]);
}

// ---------------- lean SpMM: 2 nodes per warp, float4 gathers --------------------
template <int K>
__global__ void __launch_bounds__(256) spmm_kernel(
    const float* __restrict__ h,
    const float* __restrict__ prev,
    float* __restrict__ dst,
    int n)
{
    int tid  = threadIdx.x;
    int warp = tid >> 5;
    int lane = tid & 31;
    int half = lane >> 4;
    int hl   = lane & 15;
    unsigned hmask = 0xFFFFu << (half << 4);

    int r = blockIdx.x * 16 + warp * 2 + half;
    bool valid = (r < n);

    int   s = 0, mN = 0;
    float scale = 0.0f;
    if (valid) {
        s     = g_rowstart[r];
        mN    = g_deg[r];
        scale = -g_dinv[r];
    }

    float4 acc = make_float4(0.0f, 0.0f, 0.0f, 0.0f);

    for (int base = 0; base < mN; base += 16) {
        int m = mN - base;
        if (m > 16) m = 16;
        float2 ev = make_float2(0.0f, 0.0f);
        if (hl < m) ev = g_edge[s + base + hl];
        int   cl = __float_as_int(ev.x);
        float ll = ev.y;

        int j = 0;
        for (; j + 4 <= m; j += 4) {
            int c0 = __shfl_sync(hmask, cl, j + 0, 16);
            int c1 = __shfl_sync(hmask, cl, j + 1, 16);
            int c2 = __shfl_sync(hmask, cl, j + 2, 16);
            int c3 = __shfl_sync(hmask, cl, j + 3, 16);
            float l0 = __shfl_sync(hmask, ll, j + 0, 16);
            float l1 = __shfl_sync(hmask, ll, j + 1, 16);
            float l2 = __shfl_sync(hmask, ll, j + 2, 16);
            float l3 = __shfl_sync(hmask, ll, j + 3, 16);
            float4 h0 = *(const float4*)(h + (size_t)c0 * D + hl * 4);
            float4 h1 = *(const float4*)(h + (size_t)c1 * D + hl * 4);
            float4 h2 = *(const float4*)(h + (size_t)c2 * D + hl * 4);
            float4 h3 = *(const float4*)(h + (size_t)c3 * D + hl * 4);
            acc.x = fmaf(l0, h0.x, acc.x); acc.y = fmaf(l0, h0.y, acc.y);
            acc.z = fmaf(l0, h0.z, acc.z); acc.w = fmaf(l0, h0.w, acc.w);
            acc.x = fmaf(l1, h1.x, acc.x); acc.y = fmaf(l1, h1.y, acc.y);
            acc.z = fmaf(l1, h1.z, acc.z); acc.w = fmaf(l1, h1.w, acc.w);
            acc.x = fmaf(l2, h2.x, acc.x); acc.y = fmaf(l2, h2.y, acc.y);
            acc.z = fmaf(l2, h2.z, acc.z); acc.w = fmaf(l2, h2.w, acc.w);
            acc.x = fmaf(l3, h3.x, acc.x); acc.y = fmaf(l3, h3.y, acc.y);
            acc.z = fmaf(l3, h3.z, acc.z); acc.w = fmaf(l3, h3.w, acc.w);
        }
        for (; j < m; ++j) {
            int   cj = __shfl_sync(hmask, cl, j, 16);
            float lj = __shfl_sync(hmask, ll, j, 16);
            float4 hv = *(const float4*)(h + (size_t)cj * D + hl * 4);
            acc.x = fmaf(lj, hv.x, acc.x); acc.y = fmaf(lj, hv.y, acc.y);
            acc.z = fmaf(lj, hv.z, acc.z); acc.w = fmaf(lj, hv.w, acc.w);
        }
    }

    if (!valid) return;

    float4 t;
    if constexpr (K == 1) {
        t = make_float4(scale * acc.x, scale * acc.y, scale * acc.z, scale * acc.w);
    } else {
        float4 pv = *(const float4*)(prev + (size_t)r * D + hl * 4);
        float s2 = 2.0f * scale;
        t = make_float4(fmaf(s2, acc.x, -pv.x), fmaf(s2, acc.y, -pv.y),
                        fmaf(s2, acc.z, -pv.z), fmaf(s2, acc.w, -pv.w));
    }
    *(float4*)(dst + (size_t)r * D + hl * 4) = t;
}

// ---------------- TF32 tensor-core GEMM: out = [x|T1|T2|T3] @ W(256x64) + bias ---
// Block: 128 rows x 64 cols, 8 warps. Warp: 16 rows x 64 cols via m16n8k8 HMMA.
// Inputs rounded to tf32 (cvt.rna) at staging time; accumulation in fp32.
#define GROWS 128

__device__ __forceinline__ uint32_t f2tf(float f) {
    uint32_t r;
    asm("cvt.rna.tf32.f32 %0, %1;" : "=r"(r) : "f"(f));
    return r;
}

__global__ void __launch_bounds__(256) gemm_tf32(
    const float* __restrict__ x,
    const float* __restrict__ w,      // [4][64][64] stacked
    const float* __restrict__ bias,
    float* __restrict__ out,
    int n)
{
    __shared__ uint32_t sA[GROWS][36];   // A half-chunk (tf32 bits), pad 36 -> conflict-free
    __shared__ uint32_t sW[32][72];      // W half-chunk, pad 72 -> conflict-free

    int tid  = threadIdx.x;
    int lane = tid & 31;
    int warp = tid >> 5;
    int g    = lane >> 2;          // groupID 0..7
    int tg   = lane & 3;           // thread-in-group 0..3
    int base = blockIdx.x * GROWS;

    float c[8][4];
#pragma unroll
    for (int j = 0; j < 8; ++j)
#pragma unroll
        for (int i = 0; i < 4; ++i) c[j][i] = 0.0f;

    const float* srcs[4] = { x, g_tx1, g_tx2, g_tx3 };

#pragma unroll
    for (int chunk = 0; chunk < 4; ++chunk) {
        const float* src = srcs[chunk];
        const float* wc  = w + chunk * (D * D);
#pragma unroll
        for (int h = 0; h < 2; ++h) {
            __syncthreads();
            // stage W half: k in [32h, 32h+32), 2048 floats
#pragma unroll
            for (int i = 0; i < 2; ++i) {
                int i4 = tid + i * 256;                  // 0..511 float4s
                float4 v = *(const float4*)(wc + h * 2048 + i4 * 4);
                int k   = i4 >> 4;
                int col = (i4 & 15) * 4;
                sW[k][col + 0] = f2tf(v.x);
                sW[k][col + 1] = f2tf(v.y);
                sW[k][col + 2] = f2tf(v.z);
                sW[k][col + 3] = f2tf(v.w);
            }
            // stage A half: 128 rows x 32 k
            {
                int m      = tid >> 1;
                int half16 = (tid & 1) * 16;
                int row    = base + m;
#pragma unroll
                for (int q = 0; q < 4; ++q) {
                    float4 v = make_float4(0.f, 0.f, 0.f, 0.f);
                    if (row < n)
                        v = *(const float4*)(src + (size_t)row * D + h * 32 + half16 + q * 4);
                    int kc = half16 + q * 4;
                    sA[m][kc + 0] = f2tf(v.x);
                    sA[m][kc + 1] = f2tf(v.y);
                    sA[m][kc + 2] = f2tf(v.z);
                    sA[m][kc + 3] = f2tf(v.w);
                }
            }
            __syncthreads();

#pragma unroll
            for (int k0 = 0; k0 < 32; k0 += 8) {
                uint32_t a0 = sA[warp * 16 + g    ][k0 + tg];
                uint32_t a1 = sA[warp * 16 + g + 8][k0 + tg];
                uint32_t a2 = sA[warp * 16 + g    ][k0 + tg + 4];
                uint32_t a3 = sA[warp * 16 + g + 8][k0 + tg + 4];
#pragma unroll
                for (int j = 0; j < 8; ++j) {
                    uint32_t b0 = sW[k0 + tg    ][j * 8 + g];
                    uint32_t b1 = sW[k0 + tg + 4][j * 8 + g];
                    asm volatile(
                        "mma.sync.aligned.m16n8k8.row.col.f32.tf32.tf32.f32 "
                        "{%0,%1,%2,%3}, {%4,%5,%6,%7}, {%8,%9}, {%0,%1,%2,%3};"
                        : "+f"(c[j][0]), "+f"(c[j][1]), "+f"(c[j][2]), "+f"(c[j][3])
                        : "r"(a0), "r"(a1), "r"(a2), "r"(a3), "r"(b0), "r"(b1));
                }
            }
        }
    }

    // epilogue: C frag (row = 16*warp + g (+8), col = 8j + 2*tg (+1)) + bias
    int r0 = base + warp * 16 + g;
    int r1 = r0 + 8;
#pragma unroll
    for (int j = 0; j < 8; ++j) {
        int col  = j * 8 + tg * 2;
        float bx = __ldg(bias + col);
        float by = __ldg(bias + col + 1);
        if (r0 < n) {
            float2 v = make_float2(c[j][0] + bx, c[j][1] + by);
            *(float2*)(out + (size_t)r0 * D + col) = v;
        }
        if (r1 < n) {
            float2 v = make_float2(c[j][2] + bx, c[j][3] + by);
            *(float2*)(out + (size_t)r1 * D + col) = v;
        }
    }
}

// ---------------- launch -----------------------------------------------------------
extern "C" void kernel_launch(void* const* d_in, const int* in_sizes, int n_in,
                              void* d_out, int out_size)
{
    const float* x   = (const float*)d_in[0];
    const void*  ei  = d_in[1];
    const float* ea  = (const float*)d_in[2];
    const float* w   = (const float*)d_in[3];
    const float* b   = (const float*)d_in[4];
    float*       out = (float*)d_out;

    int n = in_sizes[0] / D;
    int E = in_sizes[2];

    int nbN = (n + 255) / 256;
    int nbE = (E + 255) / 256;

    float *tx1, *tx2, *tx3;
    cudaGetSymbolAddress((void**)&tx1, g_tx1);
    cudaGetSymbolAddress((void**)&tx2, g_tx2);
    cudaGetSymbolAddress((void**)&tx3, g_tx3);

    void* degp; cudaGetSymbolAddress(&degp, g_deg);
    cudaMemsetAsync(degp, 0, (size_t)n * sizeof(int));

    k_detect<<<1, 256>>>(ei, n);
    k_prep<<<nbE, 256>>>(ei, E);
    k_offsets<<<nbN, 256>>>(n);
    k_scatter<<<nbE, 256>>>(ei, ea, E);

    int gs = (n + 15) / 16;   // 16 nodes per block (2 per warp)
    spmm_kernel<1><<<gs, 256>>>(x,   nullptr, tx1, n);
    spmm_kernel<2><<<gs, 256>>>(tx1, x,       tx2, n);
    spmm_kernel<3><<<gs, 256>>>(tx2, tx1,     tx3, n);

    gemm_tf32<<<(n + GROWS - 1) / GROWS, 256>>>(x, w, b, out, n);
}

// round 12
// speedup vs baseline: 2.3772x; 1.0622x over previous
#include <cuda_runtime.h>
#include <cuda_fp16.h>
#include <stdint.h>

#define N_MAX   100000
#define E_MAX   1600000
#define D       64

// ---------------- scratch (static device globals; no allocations) -------------
__device__ int    g_is64;
__device__ int    g_total;
__device__ int    g_deg[N_MAX];
__device__ float  g_dinv[N_MAX];
__device__ int    g_rowstart[N_MAX];
__device__ int    g_cursor[N_MAX];
__device__ float2 g_edge[E_MAX];                  // {col(bits), ea*dinv[col]}
__device__ __half g_hx [(size_t)N_MAX * D];       // fp16 copy of x
__device__ __half g_t1 [(size_t)N_MAX * D];
__device__ __half g_t2 [(size_t)N_MAX * D];
__device__ __half g_t3 [(size_t)N_MAX * D];

// ---------------- prep -----------------------------------------------------------
__global__ void k_detect(const void* __restrict__ ei_raw, int n) {
    if (threadIdx.x == 0) { g_total = 0; g_is64 = 1; }
    __syncthreads();
    const long long* e64 = (const long long*)ei_raw;
    long long v = e64[threadIdx.x];
    if (v < 0 || v >= (long long)n) g_is64 = 0;   // any OOB => int32 data
}

__global__ void k_prep(const void* __restrict__ ei_raw, int E) {
    int e = blockIdx.x * blockDim.x + threadIdx.x;
    if (e >= E) return;
    int r;
    if (g_is64) r = (int)((const long long*)ei_raw)[e];
    else        r = ((const int*)ei_raw)[e];
    atomicAdd(&g_deg[r], 1);
}

__global__ void k_offsets(int n) {
    int i = blockIdx.x * blockDim.x + threadIdx.x;
    if (i >= n) return;
    int dg = g_deg[i];
    int st = atomicAdd(&g_total, dg);
    g_rowstart[i] = st;
    g_cursor[i]   = st;
    g_dinv[i]     = (dg > 0) ? rsqrtf((float)dg) : 0.0f;
}

__global__ void k_scatter(const void* __restrict__ ei_raw,
                          const float* __restrict__ ea, int E) {
    int e = blockIdx.x * blockDim.x + threadIdx.x;
    if (e >= E) return;
    int r, c;
    if (g_is64) {
        const long long* ei = (const long long*)ei_raw;
        r = (int)ei[e];
        c = (int)ei[(size_t)E + e];
    } else {
        const int* ei = (const int*)ei_raw;
        r = ei[e];
        c = ei[(size_t)E + e];
    }
    int p = atomicAdd(&g_cursor[r], 1);
    g_edge[p] = make_float2(__int_as_float(c), ea[e] * g_dinv[c]);
}

// x (fp32) -> fp16 copy
__global__ void k_f2h(const float* __restrict__ src, int total4) {
    int i = blockIdx.x * 256 + threadIdx.x;
    if (i >= total4) return;
    float4 v = ((const float4*)src)[i];
    __half2 a = __floats2half2_rn(v.x, v.y);
    __half2 b = __floats2half2_rn(v.z, v.w);
    ((__half2*)g_hx)[i * 2 + 0] = a;
    ((__half2*)g_hx)[i * 2 + 1] = b;
}

// ---------------- SpMM: fp16 gather, fp32 accumulate, fp16 store ------------------
// 2 nodes per warp, 16 lanes per node, 8B (4 halves) per lane -> 128B per row.
//   acc = sum_e (ea*dinv[c]) * h[c];  t = (-dinv[r])*acc            (K==1)
//                                      t = 2*(-dinv[r])*acc - prev   (K>=2)
template <int K>
__global__ void __launch_bounds__(256) spmm_kernel(
    const __half* __restrict__ h,
    const __half* __restrict__ prev,
    __half* __restrict__ dst,
    int n)
{
    int tid  = threadIdx.x;
    int warp = tid >> 5;
    int lane = tid & 31;
    int half = lane >> 4;
    int hl   = lane & 15;
    unsigned hmask = 0xFFFFu << (half << 4);

    int r = blockIdx.x * 16 + warp * 2 + half;
    bool valid = (r < n);

    int   s = 0, mN = 0;
    float scale = 0.0f;
    if (valid) {
        s     = g_rowstart[r];
        mN    = g_deg[r];
        scale = -g_dinv[r];
    }

    float4 acc = make_float4(0.0f, 0.0f, 0.0f, 0.0f);

    for (int base = 0; base < mN; base += 16) {
        int m = mN - base;
        if (m > 16) m = 16;
        float2 ev = make_float2(0.0f, 0.0f);
        if (hl < m) ev = g_edge[s + base + hl];
        int   cl = __float_as_int(ev.x);
        float ll = ev.y;

        for (int j = 0; j < m; ++j) {
            int   cj = __shfl_sync(hmask, cl, j, 16);
            float lj = __shfl_sync(hmask, ll, j, 16);
            uint2 u = *(const uint2*)(h + (size_t)cj * D + hl * 4);
            float2 f0 = __half22float2(*(__half2*)&u.x);
            float2 f1 = __half22float2(*(__half2*)&u.y);
            acc.x = fmaf(lj, f0.x, acc.x); acc.y = fmaf(lj, f0.y, acc.y);
            acc.z = fmaf(lj, f1.x, acc.z); acc.w = fmaf(lj, f1.y, acc.w);
        }
    }

    if (!valid) return;

    float4 t;
    if constexpr (K == 1) {
        t = make_float4(scale * acc.x, scale * acc.y, scale * acc.z, scale * acc.w);
    } else {
        uint2 pu = *(const uint2*)(prev + (size_t)r * D + hl * 4);
        float2 p0 = __half22float2(*(__half2*)&pu.x);
        float2 p1 = __half22float2(*(__half2*)&pu.y);
        float s2 = 2.0f * scale;
        t = make_float4(fmaf(s2, acc.x, -p0.x), fmaf(s2, acc.y, -p0.y),
                        fmaf(s2, acc.z, -p1.x), fmaf(s2, acc.w, -p1.y));
    }
    __half2 o0 = __floats2half2_rn(t.x, t.y);
    __half2 o1 = __floats2half2_rn(t.z, t.w);
    uint2 st = make_uint2(*(uint32_t*)&o0, *(uint32_t*)&o1);
    *(uint2*)(dst + (size_t)r * D + hl * 4) = st;
}

// ---------------- TF32 tensor GEMM: out = [x|T1|T2|T3] @ W(256x64) + bias ---------
// A sources are fp16 (fp16 -> tf32 is exact: both 10 explicit mantissa bits).
#define GROWS 128

__device__ __forceinline__ uint32_t f2tf(float f) {
    uint32_t r;
    asm("cvt.rna.tf32.f32 %0, %1;" : "=r"(r) : "f"(f));
    return r;
}

__global__ void __launch_bounds__(256) gemm_tf32(
    const float* __restrict__ w,      // [4][64][64] stacked
    const float* __restrict__ bias,
    float* __restrict__ out,
    int n)
{
    __shared__ uint32_t sA[GROWS][36];   // pad 36 -> conflict-free
    __shared__ uint32_t sW[32][72];      // pad 72 -> conflict-free

    int tid  = threadIdx.x;
    int lane = tid & 31;
    int warp = tid >> 5;
    int g    = lane >> 2;
    int tg   = lane & 3;
    int base = blockIdx.x * GROWS;

    float c[8][4];
#pragma unroll
    for (int j = 0; j < 8; ++j)
#pragma unroll
        for (int i = 0; i < 4; ++i) c[j][i] = 0.0f;

    const __half* srcs[4] = { g_hx, g_t1, g_t2, g_t3 };

#pragma unroll
    for (int chunk = 0; chunk < 4; ++chunk) {
        const __half* src = srcs[chunk];
        const float*  wc  = w + chunk * (D * D);
#pragma unroll
        for (int h = 0; h < 2; ++h) {
            __syncthreads();
            // stage W half: k in [32h, 32h+32)
#pragma unroll
            for (int i = 0; i < 2; ++i) {
                int i4 = tid + i * 256;
                float4 v = *(const float4*)(wc + h * 2048 + i4 * 4);
                int k   = i4 >> 4;
                int col = (i4 & 15) * 4;
                sW[k][col + 0] = f2tf(v.x);
                sW[k][col + 1] = f2tf(v.y);
                sW[k][col + 2] = f2tf(v.z);
                sW[k][col + 3] = f2tf(v.w);
            }
            // stage A half: 128 rows x 32 k (fp16 source)
            {
                int m      = tid >> 1;
                int half16 = (tid & 1) << 4;
                int row    = base + m;
                const __half* sp = src + (size_t)row * D + h * 32 + half16;
                uint4 u0 = make_uint4(0, 0, 0, 0), u1 = make_uint4(0, 0, 0, 0);
                if (row < n) {
                    u0 = *(const uint4*)sp;        // 8 halves
                    u1 = *(const uint4*)(sp + 8);  // 8 halves
                }
                const uint32_t* up = &u0.x;
#pragma unroll
                for (int q = 0; q < 8; ++q) {
                    uint32_t pk = (q < 4) ? up[q] : (&u1.x)[q - 4];
                    float2 f = __half22float2(*(__half2*)&pk);
                    sA[m][half16 + q * 2 + 0] = f2tf(f.x);
                    sA[m][half16 + q * 2 + 1] = f2tf(f.y);
                }
            }
            __syncthreads();

#pragma unroll
            for (int k0 = 0; k0 < 32; k0 += 8) {
                uint32_t a0 = sA[warp * 16 + g    ][k0 + tg];
                uint32_t a1 = sA[warp * 16 + g + 8][k0 + tg];
                uint32_t a2 = sA[warp * 16 + g    ][k0 + tg + 4];
                uint32_t a3 = sA[warp * 16 + g + 8][k0 + tg + 4];
#pragma unroll
                for (int j = 0; j < 8; ++j) {
                    uint32_t b0 = sW[k0 + tg    ][j * 8 + g];
                    uint32_t b1 = sW[k0 + tg + 4][j * 8 + g];
                    asm volatile(
                        "mma.sync.aligned.m16n8k8.row.col.f32.tf32.tf32.f32 "
                        "{%0,%1,%2,%3}, {%4,%5,%6,%7}, {%8,%9}, {%0,%1,%2,%3};"
                        : "+f"(c[j][0]), "+f"(c[j][1]), "+f"(c[j][2]), "+f"(c[j][3])
                        : "r"(a0), "r"(a1), "r"(a2), "r"(a3), "r"(b0), "r"(b1));
                }
            }
        }
    }

    int r0 = base + warp * 16 + g;
    int r1 = r0 + 8;
#pragma unroll
    for (int j = 0; j < 8; ++j) {
        int col  = j * 8 + tg * 2;
        float bx = __ldg(bias + col);
        float by = __ldg(bias + col + 1);
        if (r0 < n) {
            float2 v = make_float2(c[j][0] + bx, c[j][1] + by);
            *(float2*)(out + (size_t)r0 * D + col) = v;
        }
        if (r1 < n) {
            float2 v = make_float2(c[j][2] + bx, c[j][3] + by);
            *(float2*)(out + (size_t)r1 * D + col) = v;
        }
    }
}

// ---------------- launch -----------------------------------------------------------
extern "C" void kernel_launch(void* const* d_in, const int* in_sizes, int n_in,
                              void* d_out, int out_size)
{
    const float* x   = (const float*)d_in[0];
    const void*  ei  = d_in[1];
    const float* ea  = (const float*)d_in[2];
    const float* w   = (const float*)d_in[3];
    const float* b   = (const float*)d_in[4];
    float*       out = (float*)d_out;

    int n = in_sizes[0] / D;
    int E = in_sizes[2];

    int nbN = (n + 255) / 256;
    int nbE = (E + 255) / 256;

    __half *hx, *t1, *t2, *t3;
    cudaGetSymbolAddress((void**)&hx, g_hx);
    cudaGetSymbolAddress((void**)&t1, g_t1);
    cudaGetSymbolAddress((void**)&t2, g_t2);
    cudaGetSymbolAddress((void**)&t3, g_t3);

    void* degp; cudaGetSymbolAddress(&degp, g_deg);
    cudaMemsetAsync(degp, 0, (size_t)n * sizeof(int));

    k_detect<<<1, 256>>>(ei, n);
    k_f2h<<<(n * (D / 4) + 255) / 256, 256>>>(x, n * (D / 4));
    k_prep<<<nbE, 256>>>(ei, E);
    k_offsets<<<nbN, 256>>>(n);
    k_scatter<<<nbE, 256>>>(ei, ea, E);

    int gs = (n + 15) / 16;   // 16 nodes per block (2 per warp)
    spmm_kernel<1><<<gs, 256>>>(hx, nullptr, t1, n);
    spmm_kernel<2><<<gs, 256>>>(t1, hx,      t2, n);
    spmm_kernel<3><<<gs, 256>>>(t2, t1,      t3, n);

    gemm_tf32<<<(n + GROWS - 1) / GROWS, 256>>>(w, b, out, n);
}

// round 14
// speedup vs baseline: 2.4578x; 1.0339x over previous
#include <cuda_runtime.h>
#include <cuda_fp16.h>
#include <stdint.h>

#define N_MAX   100000
#define E_MAX   1600000
#define D       64

// ---------------- scratch (static device globals; no allocations) -------------
__device__ int    g_is64;
__device__ int    g_total;
__device__ int    g_deg[N_MAX];
__device__ float  g_dinv[N_MAX];
__device__ int    g_rowstart[N_MAX];
__device__ int    g_cursor[N_MAX];
__device__ float2 g_edge[E_MAX];                  // {col(bits), ea*dinv[col]}
__device__ __half g_hx [(size_t)N_MAX * D];       // fp16 copy of x
__device__ __half g_t1 [(size_t)N_MAX * D];
__device__ __half g_t2 [(size_t)N_MAX * D];
__device__ __half g_t3 [(size_t)N_MAX * D];

// ---------------- prep -----------------------------------------------------------
__global__ void k_detect(const void* __restrict__ ei_raw, int n) {
    if (threadIdx.x == 0) { g_total = 0; g_is64 = 1; }
    __syncthreads();
    const long long* e64 = (const long long*)ei_raw;
    long long v = e64[threadIdx.x];
    if (v < 0 || v >= (long long)n) g_is64 = 0;   // any OOB => int32 data
}

__global__ void k_prep(const void* __restrict__ ei_raw, int E) {
    int e = blockIdx.x * blockDim.x + threadIdx.x;
    if (e >= E) return;
    int r;
    if (g_is64) r = (int)((const long long*)ei_raw)[e];
    else        r = ((const int*)ei_raw)[e];
    atomicAdd(&g_deg[r], 1);
}

__global__ void k_offsets(int n) {
    int i = blockIdx.x * blockDim.x + threadIdx.x;
    if (i >= n) return;
    int dg = g_deg[i];
    int st = atomicAdd(&g_total, dg);
    g_rowstart[i] = st;
    g_cursor[i]   = st;
    g_dinv[i]     = (dg > 0) ? rsqrtf((float)dg) : 0.0f;
}

__global__ void k_scatter(const void* __restrict__ ei_raw,
                          const float* __restrict__ ea, int E) {
    int e = blockIdx.x * blockDim.x + threadIdx.x;
    if (e >= E) return;
    int r, c;
    if (g_is64) {
        const long long* ei = (const long long*)ei_raw;
        r = (int)ei[e];
        c = (int)ei[(size_t)E + e];
    } else {
        const int* ei = (const int*)ei_raw;
        r = ei[e];
        c = ei[(size_t)E + e];
    }
    int p = atomicAdd(&g_cursor[r], 1);
    g_edge[p] = make_float2(__int_as_float(c), ea[e] * g_dinv[c]);
}

// x (fp32) -> fp16 copy
__global__ void k_f2h(const float* __restrict__ src, int total4) {
    int i = blockIdx.x * 256 + threadIdx.x;
    if (i >= total4) return;
    float4 v = ((const float4*)src)[i];
    __half2 a = __floats2half2_rn(v.x, v.y);
    __half2 b = __floats2half2_rn(v.z, v.w);
    ((__half2*)g_hx)[i * 2 + 0] = a;
    ((__half2*)g_hx)[i * 2 + 1] = b;
}

// ---------------- SpMM: fp16 gather (4-deep MLP), fp32 accumulate, fp16 store -----
// 2 nodes per warp, 16 lanes per node, 8B (4 halves) per lane -> 128B per row.
template <int K>
__global__ void __launch_bounds__(256) spmm_kernel(
    const __half* __restrict__ h,
    const __half* __restrict__ prev,
    __half* __restrict__ dst,
    int n)
{
    int tid  = threadIdx.x;
    int warp = tid >> 5;
    int lane = tid & 31;
    int half = lane >> 4;
    int hl   = lane & 15;
    unsigned hmask = 0xFFFFu << (half << 4);

    int r = blockIdx.x * 16 + warp * 2 + half;
    bool valid = (r < n);

    int   s = 0, mN = 0;
    float scale = 0.0f;
    if (valid) {
        s     = g_rowstart[r];
        mN    = g_deg[r];
        scale = -g_dinv[r];
    }

    float4 acc = make_float4(0.0f, 0.0f, 0.0f, 0.0f);

    // prefetch first edge chunk
    float2 ev = make_float2(0.0f, 0.0f);
    if (hl < mN) ev = g_edge[s + hl];

    for (int base = 0; base < mN; base += 16) {
        int m = mN - base;
        if (m > 16) m = 16;
        int   cl = __float_as_int(ev.x);
        float ll = ev.y;

        // prefetch next chunk while current loads are in flight
        int nb = base + 16;
        if (nb + hl < mN) ev = g_edge[s + nb + hl];
        else              ev = make_float2(0.0f, 0.0f);

        int j = 0;
        for (; j + 4 <= m; j += 4) {
            int c0 = __shfl_sync(hmask, cl, j + 0, 16);
            int c1 = __shfl_sync(hmask, cl, j + 1, 16);
            int c2 = __shfl_sync(hmask, cl, j + 2, 16);
            int c3 = __shfl_sync(hmask, cl, j + 3, 16);
            float l0 = __shfl_sync(hmask, ll, j + 0, 16);
            float l1 = __shfl_sync(hmask, ll, j + 1, 16);
            float l2 = __shfl_sync(hmask, ll, j + 2, 16);
            float l3 = __shfl_sync(hmask, ll, j + 3, 16);
            // 4 independent 8B gathers in flight
            uint2 u0 = *(const uint2*)(h + (size_t)c0 * D + hl * 4);
            uint2 u1 = *(const uint2*)(h + (size_t)c1 * D + hl * 4);
            uint2 u2 = *(const uint2*)(h + (size_t)c2 * D + hl * 4);
            uint2 u3 = *(const uint2*)(h + (size_t)c3 * D + hl * 4);
            float2 a0 = __half22float2(*(__half2*)&u0.x);
            float2 b0 = __half22float2(*(__half2*)&u0.y);
            float2 a1 = __half22float2(*(__half2*)&u1.x);
            float2 b1 = __half22float2(*(__half2*)&u1.y);
            float2 a2 = __half22float2(*(__half2*)&u2.x);
            float2 b2 = __half22float2(*(__half2*)&u2.y);
            float2 a3 = __half22float2(*(__half2*)&u3.x);
            float2 b3 = __half22float2(*(__half2*)&u3.y);
            acc.x = fmaf(l0, a0.x, acc.x); acc.y = fmaf(l0, a0.y, acc.y);
            acc.z = fmaf(l0, b0.x, acc.z); acc.w = fmaf(l0, b0.y, acc.w);
            acc.x = fmaf(l1, a1.x, acc.x); acc.y = fmaf(l1, a1.y, acc.y);
            acc.z = fmaf(l1, b1.x, acc.z); acc.w = fmaf(l1, b1.y, acc.w);
            acc.x = fmaf(l2, a2.x, acc.x); acc.y = fmaf(l2, a2.y, acc.y);
            acc.z = fmaf(l2, b2.x, acc.z); acc.w = fmaf(l2, b2.y, acc.w);
            acc.x = fmaf(l3, a3.x, acc.x); acc.y = fmaf(l3, a3.y, acc.y);
            acc.z = fmaf(l3, b3.x, acc.z); acc.w = fmaf(l3, b3.y, acc.w);
        }
        for (; j < m; ++j) {
            int   cj = __shfl_sync(hmask, cl, j, 16);
            float lj = __shfl_sync(hmask, ll, j, 16);
            uint2 u = *(const uint2*)(h + (size_t)cj * D + hl * 4);
            float2 f0 = __half22float2(*(__half2*)&u.x);
            float2 f1 = __half22float2(*(__half2*)&u.y);
            acc.x = fmaf(lj, f0.x, acc.x); acc.y = fmaf(lj, f0.y, acc.y);
            acc.z = fmaf(lj, f1.x, acc.z); acc.w = fmaf(lj, f1.y, acc.w);
        }
    }

    if (!valid) return;

    float4 t;
    if constexpr (K == 1) {
        t = make_float4(scale * acc.x, scale * acc.y, scale * acc.z, scale * acc.w);
    } else {
        uint2 pu = *(const uint2*)(prev + (size_t)r * D + hl * 4);
        float2 p0 = __half22float2(*(__half2*)&pu.x);
        float2 p1 = __half22float2(*(__half2*)&pu.y);
        float s2 = 2.0f * scale;
        t = make_float4(fmaf(s2, acc.x, -p0.x), fmaf(s2, acc.y, -p0.y),
                        fmaf(s2, acc.z, -p1.x), fmaf(s2, acc.w, -p1.y));
    }
    __half2 o0 = __floats2half2_rn(t.x, t.y);
    __half2 o1 = __floats2half2_rn(t.z, t.w);
    uint2 st = make_uint2(*(uint32_t*)&o0, *(uint32_t*)&o1);
    *(uint2*)(dst + (size_t)r * D + hl * 4) = st;
}

// ---------------- TF32 tensor GEMM: out = [x|T1|T2|T3] @ W(256x64) + bias ---------
#define GROWS 128

__device__ __forceinline__ uint32_t f2tf(float f) {
    uint32_t r;
    asm("cvt.rna.tf32.f32 %0, %1;" : "=r"(r) : "f"(f));
    return r;
}

__global__ void __launch_bounds__(256) gemm_tf32(
    const float* __restrict__ w,      // [4][64][64] stacked
    const float* __restrict__ bias,
    float* __restrict__ out,
    int n)
{
    __shared__ uint32_t sA[GROWS][36];
    __shared__ uint32_t sW[32][72];

    int tid  = threadIdx.x;
    int lane = tid & 31;
    int warp = tid >> 5;
    int g    = lane >> 2;
    int tg   = lane & 3;
    int base = blockIdx.x * GROWS;

    float c[8][4];
#pragma unroll
    for (int j = 0; j < 8; ++j)
#pragma unroll
        for (int i = 0; i < 4; ++i) c[j][i] = 0.0f;

    const __half* srcs[4] = { g_hx, g_t1, g_t2, g_t3 };

#pragma unroll
    for (int chunk = 0; chunk < 4; ++chunk) {
        const __half* src = srcs[chunk];
        const float*  wc  = w + chunk * (D * D);
#pragma unroll
        for (int h = 0; h < 2; ++h) {
            __syncthreads();
#pragma unroll
            for (int i = 0; i < 2; ++i) {
                int i4 = tid + i * 256;
                float4 v = *(const float4*)(wc + h * 2048 + i4 * 4);
                int k   = i4 >> 4;
                int col = (i4 & 15) * 4;
                sW[k][col + 0] = f2tf(v.x);
                sW[k][col + 1] = f2tf(v.y);
                sW[k][col + 2] = f2tf(v.z);
                sW[k][col + 3] = f2tf(v.w);
            }
            {
                int m      = tid >> 1;
                int half16 = (tid & 1) << 4;
                int row    = base + m;
                const __half* sp = src + (size_t)row * D + h * 32 + half16;
                uint4 u0 = make_uint4(0, 0, 0, 0), u1 = make_uint4(0, 0, 0, 0);
                if (row < n) {
                    u0 = *(const uint4*)sp;
                    u1 = *(const uint4*)(sp + 8);
                }
#pragma unroll
                for (int q = 0; q < 8; ++q) {
                    uint32_t pk = (q < 4) ? (&u0.x)[q] : (&u1.x)[q - 4];
                    float2 f = __half22float2(*(__half2*)&pk);
                    sA[m][half16 + q * 2 + 0] = f2tf(f.x);
                    sA[m][half16 + q * 2 + 1] = f2tf(f.y);
                }
            }
            __syncthreads();

#pragma unroll
            for (int k0 = 0; k0 < 32; k0 += 8) {
                uint32_t a0 = sA[warp * 16 + g    ][k0 + tg];
                uint32_t a1 = sA[warp * 16 + g + 8][k0 + tg];
                uint32_t a2 = sA[warp * 16 + g    ][k0 + tg + 4];
                uint32_t a3 = sA[warp * 16 + g + 8][k0 + tg + 4];
#pragma unroll
                for (int j = 0; j < 8; ++j) {
                    uint32_t b0 = sW[k0 + tg    ][j * 8 + g];
                    uint32_t b1 = sW[k0 + tg + 4][j * 8 + g];
                    asm volatile(
                        "mma.sync.aligned.m16n8k8.row.col.f32.tf32.tf32.f32 "
                        "{%0,%1,%2,%3}, {%4,%5,%6,%7}, {%8,%9}, {%0,%1,%2,%3};"
                        : "+f"(c[j][0]), "+f"(c[j][1]), "+f"(c[j][2]), "+f"(c[j][3])
                        : "r"(a0), "r"(a1), "r"(a2), "r"(a3), "r"(b0), "r"(b1));
                }
            }
        }
    }

    int r0 = base + warp * 16 + g;
    int r1 = r0 + 8;
#pragma unroll
    for (int j = 0; j < 8; ++j) {
        int col  = j * 8 + tg * 2;
        float bx = __ldg(bias + col);
        float by = __ldg(bias + col + 1);
        if (r0 < n) {
            float2 v = make_float2(c[j][0] + bx, c[j][1] + by);
            *(float2*)(out + (size_t)r0 * D + col) = v;
        }
        if (r1 < n) {
            float2 v = make_float2(c[j][2] + bx, c[j][3] + by);
            *(float2*)(out + (size_t)r1 * D + col) = v;
        }
    }
}

// ---------------- launch -----------------------------------------------------------
extern "C" void kernel_launch(void* const* d_in, const int* in_sizes, int n_in,
                              void* d_out, int out_size)
{
    const float* x   = (const float*)d_in[0];
    const void*  ei  = d_in[1];
    const float* ea  = (const float*)d_in[2];
    const float* w   = (const float*)d_in[3];
    const float* b   = (const float*)d_in[4];
    float*       out = (float*)d_out;

    int n = in_sizes[0] / D;
    int E = in_sizes[2];

    int nbN = (n + 255) / 256;
    int nbE = (E + 255) / 256;

    __half *hx, *t1, *t2, *t3;
    cudaGetSymbolAddress((void**)&hx, g_hx);
    cudaGetSymbolAddress((void**)&t1, g_t1);
    cudaGetSymbolAddress((void**)&t2, g_t2);
    cudaGetSymbolAddress((void**)&t3, g_t3);

    void* degp; cudaGetSymbolAddress(&degp, g_deg);
    cudaMemsetAsync(degp, 0, (size_t)n * sizeof(int));

    k_detect<<<1, 256>>>(ei, n);
    k_f2h<<<(n * (D / 4) + 255) / 256, 256>>>(x, n * (D / 4));
    k_prep<<<nbE, 256>>>(ei, E);
    k_offsets<<<nbN, 256>>>(n);
    k_scatter<<<nbE, 256>>>(ei, ea, E);

    int gs = (n + 15) / 16;   // 16 nodes per block (2 per warp)
    spmm_kernel<1><<<gs, 256>>>(hx, nullptr, t1, n);
    spmm_kernel<2><<<gs, 256>>>(t1, hx,      t2, n);
    spmm_kernel<3><<<gs, 256>>>(t2, t1,      t3, n);

    gemm_tf32<<<(n + GROWS - 1) / GROWS, 256>>>(w, b, out, n);
}

// round 16
// speedup vs baseline: 2.8470x; 1.1584x over previous
#include <cuda_runtime.h>
#include <cuda_fp16.h>
#include <stdint.h>

#define N_MAX   100000
#define E_MAX   1600000
#define E_PAD   (E_MAX + 8 * N_MAX)     // per-node segments padded to multiple of 8
#define D       64

// ---------------- scratch (static device globals; no allocations) -------------
__device__ int    g_is64;
__device__ int    g_total;
__device__ int    g_deg[N_MAX];
__device__ float  g_dinv[N_MAX];
__device__ int    g_rowstart[N_MAX];
__device__ int    g_cursor[N_MAX];
__device__ float4 g_edge4[E_PAD / 2];             // {col,lap,col,lap}; 16B aligned
__device__ __half g_hx [(size_t)N_MAX * D];       // fp16 copy of x
__device__ __half g_t1 [(size_t)N_MAX * D];
__device__ __half g_t2 [(size_t)N_MAX * D];
__device__ __half g_t3 [(size_t)N_MAX * D];

// ---------------- prep -----------------------------------------------------------
__global__ void k_detect(const void* __restrict__ ei_raw, int n) {
    if (threadIdx.x == 0) { g_total = 0; g_is64 = 1; }
    __syncthreads();
    const long long* e64 = (const long long*)ei_raw;
    long long v = e64[threadIdx.x];
    if (v < 0 || v >= (long long)n) g_is64 = 0;   // any OOB => int32 data
}

__global__ void k_prep(const void* __restrict__ ei_raw, int E) {
    int e = blockIdx.x * blockDim.x + threadIdx.x;
    if (e >= E) return;
    int r;
    if (g_is64) r = (int)((const long long*)ei_raw)[e];
    else        r = ((const int*)ei_raw)[e];
    atomicAdd(&g_deg[r], 1);
}

// segment allocation padded to multiple of 8; zero-fill pad slots
__global__ void k_offsets(int n) {
    int i = blockIdx.x * blockDim.x + threadIdx.x;
    if (i >= n) return;
    int dg  = g_deg[i];
    int dgp = (dg + 7) & ~7;
    int st  = atomicAdd(&g_total, dgp);
    g_rowstart[i] = st;
    g_cursor[i]   = st;
    g_dinv[i]     = (dg > 0) ? rsqrtf((float)dg) : 0.0f;
    float2* ge = (float2*)g_edge4;
    for (int q = dg; q < dgp; ++q)
        ge[st + q] = make_float2(0.0f, 0.0f);     // col=0, lap=0 (harmless)
}

__global__ void k_scatter(const void* __restrict__ ei_raw,
                          const float* __restrict__ ea, int E) {
    int e = blockIdx.x * blockDim.x + threadIdx.x;
    if (e >= E) return;
    int r, c;
    if (g_is64) {
        const long long* ei = (const long long*)ei_raw;
        r = (int)ei[e];
        c = (int)ei[(size_t)E + e];
    } else {
        const int* ei = (const int*)ei_raw;
        r = ei[e];
        c = ei[(size_t)E + e];
    }
    int p = atomicAdd(&g_cursor[r], 1);
    ((float2*)g_edge4)[p] = make_float2(__int_as_float(c), ea[e] * g_dinv[c]);
}

// x (fp32) -> fp16 copy
__global__ void k_f2h(const float* __restrict__ src, int total4) {
    int i = blockIdx.x * 256 + threadIdx.x;
    if (i >= total4) return;
    float4 v = ((const float4*)src)[i];
    __half2 a = __floats2half2_rn(v.x, v.y);
    __half2 b = __floats2half2_rn(v.z, v.w);
    ((__half2*)g_hx)[i * 2 + 0] = a;
    ((__half2*)g_hx)[i * 2 + 1] = b;
}

// ---------------- SpMM: aligned float4 edge loads, 8-deep gather pipeline ---------
// 2 nodes per warp, 16 lanes per node, 8B (4 halves) per lane -> 128B per row.
// Edge segments 8-padded & 16B-aligned: 8 edges = 4 unconditional float4 loads
// broadcast across the half-warp; pad slots {col=0,lap=0} gather row 0 harmlessly.
template <int K>
__global__ void __launch_bounds__(256) spmm_kernel(
    const __half* __restrict__ h,
    const __half* __restrict__ prev,
    __half* __restrict__ dst,
    int n)
{
    int tid  = threadIdx.x;
    int warp = tid >> 5;
    int lane = tid & 31;
    int half = lane >> 4;
    int hl   = lane & 15;

    int r = blockIdx.x * 16 + warp * 2 + half;
    bool valid = (r < n);

    int   s = 0, mNp = 0;
    float scale = 0.0f;
    if (valid) {
        s     = g_rowstart[r];               // multiple of 8
        int d = g_deg[r];
        mNp   = (d + 7) & ~7;                // padded loop bound
        scale = -g_dinv[r];
    }

    float4 acc = make_float4(0.0f, 0.0f, 0.0f, 0.0f);

    for (int jb = 0; jb < mNp; jb += 8) {
        int q4 = (s + jb) >> 1;              // float4 index, aligned by construction
        float4 p0 = g_edge4[q4 + 0];         // edges 0,1
        float4 p1 = g_edge4[q4 + 1];         // edges 2,3
        float4 p2 = g_edge4[q4 + 2];         // edges 4,5
        float4 p3 = g_edge4[q4 + 3];         // edges 6,7

        // 8 independent gathers
        uint2 u0 = *(const uint2*)(h + (size_t)__float_as_int(p0.x) * D + hl * 4);
        uint2 u1 = *(const uint2*)(h + (size_t)__float_as_int(p0.z) * D + hl * 4);
        uint2 u2 = *(const uint2*)(h + (size_t)__float_as_int(p1.x) * D + hl * 4);
        uint2 u3 = *(const uint2*)(h + (size_t)__float_as_int(p1.z) * D + hl * 4);
        uint2 u4 = *(const uint2*)(h + (size_t)__float_as_int(p2.x) * D + hl * 4);
        uint2 u5 = *(const uint2*)(h + (size_t)__float_as_int(p2.z) * D + hl * 4);
        uint2 u6 = *(const uint2*)(h + (size_t)__float_as_int(p3.x) * D + hl * 4);
        uint2 u7 = *(const uint2*)(h + (size_t)__float_as_int(p3.z) * D + hl * 4);

#define ACC(ui, lw)                                                     \
        {                                                               \
            float2 f0 = __half22float2(*(__half2*)&ui.x);               \
            float2 f1 = __half22float2(*(__half2*)&ui.y);               \
            acc.x = fmaf(lw, f0.x, acc.x);                              \
            acc.y = fmaf(lw, f0.y, acc.y);                              \
            acc.z = fmaf(lw, f1.x, acc.z);                              \
            acc.w = fmaf(lw, f1.y, acc.w);                              \
        }
        ACC(u0, p0.y) ACC(u1, p0.w) ACC(u2, p1.y) ACC(u3, p1.w)
        ACC(u4, p2.y) ACC(u5, p2.w) ACC(u6, p3.y) ACC(u7, p3.w)
#undef ACC
    }

    if (!valid) return;

    float4 t;
    if constexpr (K == 1) {
        t = make_float4(scale * acc.x, scale * acc.y, scale * acc.z, scale * acc.w);
    } else {
        uint2 pu = *(const uint2*)(prev + (size_t)r * D + hl * 4);
        float2 p0 = __half22float2(*(__half2*)&pu.x);
        float2 p1 = __half22float2(*(__half2*)&pu.y);
        float s2 = 2.0f * scale;
        t = make_float4(fmaf(s2, acc.x, -p0.x), fmaf(s2, acc.y, -p0.y),
                        fmaf(s2, acc.z, -p1.x), fmaf(s2, acc.w, -p1.y));
    }
    __half2 o0 = __floats2half2_rn(t.x, t.y);
    __half2 o1 = __floats2half2_rn(t.z, t.w);
    uint2 st = make_uint2(*(uint32_t*)&o0, *(uint32_t*)&o1);
    *(uint2*)(dst + (size_t)r * D + hl * 4) = st;
}

// ---------------- TF32 tensor GEMM: out = [x|T1|T2|T3] @ W(256x64) + bias ---------
#define GROWS 128

__device__ __forceinline__ uint32_t f2tf(float f) {
    uint32_t r;
    asm("cvt.rna.tf32.f32 %0, %1;" : "=r"(r) : "f"(f));
    return r;
}

__global__ void __launch_bounds__(256) gemm_tf32(
    const float* __restrict__ w,      // [4][64][64] stacked
    const float* __restrict__ bias,
    float* __restrict__ out,
    int n)
{
    __shared__ uint32_t sA[GROWS][36];
    __shared__ uint32_t sW[32][72];

    int tid  = threadIdx.x;
    int lane = tid & 31;
    int warp = tid >> 5;
    int g    = lane >> 2;
    int tg   = lane & 3;
    int base = blockIdx.x * GROWS;

    float c[8][4];
#pragma unroll
    for (int j = 0; j < 8; ++j)
#pragma unroll
        for (int i = 0; i < 4; ++i) c[j][i] = 0.0f;

    const __half* srcs[4] = { g_hx, g_t1, g_t2, g_t3 };

#pragma unroll
    for (int chunk = 0; chunk < 4; ++chunk) {
        const __half* src = srcs[chunk];
        const float*  wc  = w + chunk * (D * D);
#pragma unroll
        for (int h = 0; h < 2; ++h) {
            __syncthreads();
#pragma unroll
            for (int i = 0; i < 2; ++i) {
                int i4 = tid + i * 256;
                float4 v = *(const float4*)(wc + h * 2048 + i4 * 4);
                int k   = i4 >> 4;
                int col = (i4 & 15) * 4;
                sW[k][col + 0] = f2tf(v.x);
                sW[k][col + 1] = f2tf(v.y);
                sW[k][col + 2] = f2tf(v.z);
                sW[k][col + 3] = f2tf(v.w);
            }
            {
                int m      = tid >> 1;
                int half16 = (tid & 1) << 4;
                int row    = base + m;
                const __half* sp = src + (size_t)row * D + h * 32 + half16;
                uint4 u0 = make_uint4(0, 0, 0, 0), u1 = make_uint4(0, 0, 0, 0);
                if (row < n) {
                    u0 = *(const uint4*)sp;
                    u1 = *(const uint4*)(sp + 8);
                }
#pragma unroll
                for (int q = 0; q < 8; ++q) {
                    uint32_t pk = (q < 4) ? (&u0.x)[q] : (&u1.x)[q - 4];
                    float2 f = __half22float2(*(__half2*)&pk);
                    sA[m][half16 + q * 2 + 0] = f2tf(f.x);
                    sA[m][half16 + q * 2 + 1] = f2tf(f.y);
                }
            }
            __syncthreads();

#pragma unroll
            for (int k0 = 0; k0 < 32; k0 += 8) {
                uint32_t a0 = sA[warp * 16 + g    ][k0 + tg];
                uint32_t a1 = sA[warp * 16 + g + 8][k0 + tg];
                uint32_t a2 = sA[warp * 16 + g    ][k0 + tg + 4];
                uint32_t a3 = sA[warp * 16 + g + 8][k0 + tg + 4];
#pragma unroll
                for (int j = 0; j < 8; ++j) {
                    uint32_t b0 = sW[k0 + tg    ][j * 8 + g];
                    uint32_t b1 = sW[k0 + tg + 4][j * 8 + g];
                    asm volatile(
                        "mma.sync.aligned.m16n8k8.row.col.f32.tf32.tf32.f32 "
                        "{%0,%1,%2,%3}, {%4,%5,%6,%7}, {%8,%9}, {%0,%1,%2,%3};"
                        : "+f"(c[j][0]), "+f"(c[j][1]), "+f"(c[j][2]), "+f"(c[j][3])
                        : "r"(a0), "r"(a1), "r"(a2), "r"(a3), "r"(b0), "r"(b1));
                }
            }
        }
    }

    int r0 = base + warp * 16 + g;
    int r1 = r0 + 8;
#pragma unroll
    for (int j = 0; j < 8; ++j) {
        int col  = j * 8 + tg * 2;
        float bx = __ldg(bias + col);
        float by = __ldg(bias + col + 1);
        if (r0 < n) {
            float2 v = make_float2(c[j][0] + bx, c[j][1] + by);
            *(float2*)(out + (size_t)r0 * D + col) = v;
        }
        if (r1 < n) {
            float2 v = make_float2(c[j][2] + bx, c[j][3] + by);
            *(float2*)(out + (size_t)r1 * D + col) = v;
        }
    }
}

// ---------------- launch -----------------------------------------------------------
extern "C" void kernel_launch(void* const* d_in, const int* in_sizes, int n_in,
                              void* d_out, int out_size)
{
    const float* x   = (const float*)d_in[0];
    const void*  ei  = d_in[1];
    const float* ea  = (const float*)d_in[2];
    const float* w   = (const float*)d_in[3];
    const float* b   = (const float*)d_in[4];
    float*       out = (float*)d_out;

    int n = in_sizes[0] / D;
    int E = in_sizes[2];

    int nbN = (n + 255) / 256;
    int nbE = (E + 255) / 256;

    __half *hx, *t1, *t2, *t3;
    cudaGetSymbolAddress((void**)&hx, g_hx);
    cudaGetSymbolAddress((void**)&t1, g_t1);
    cudaGetSymbolAddress((void**)&t2, g_t2);
    cudaGetSymbolAddress((void**)&t3, g_t3);

    void* degp; cudaGetSymbolAddress(&degp, g_deg);
    cudaMemsetAsync(degp, 0, (size_t)n * sizeof(int));

    k_detect<<<1, 256>>>(ei, n);
    k_f2h<<<(n * (D / 4) + 255) / 256, 256>>>(x, n * (D / 4));
    k_prep<<<nbE, 256>>>(ei, E);
    k_offsets<<<nbN, 256>>>(n);
    k_scatter<<<nbE, 256>>>(ei, ea, E);

    int gs = (n + 15) / 16;   // 16 nodes per block (2 per warp)
    spmm_kernel<1><<<gs, 256>>>(hx, nullptr, t1, n);
    spmm_kernel<2><<<gs, 256>>>(t1, hx,      t2, n);
    spmm_kernel<3><<<gs, 256>>>(t2, t1,      t3, n);

    gemm_tf32<<<(n + GROWS - 1) / GROWS, 256>>>(w, b, out, n);
}